// round 4
// baseline (speedup 1.0000x reference)
#include <cuda_runtime.h>
#include <math.h>

#define DM 256
#define NH 4
#define HD 64
#define NN 768
#define MM 768

// ---- scratch (static device globals: allocation-free) ----
__device__ float g_q[NN * DM];            // q = xq@Wq.T + bq
__device__ float g_k[NN * DM];            // k' = 0.125*(xk@Wk.T + bk + bp)
__device__ float g_v[NN * DM];            // v = xv@Wv.T + bv
__device__ float g_R[NN * NH * DM];       // R[n][h][e] = 0.125 * sum_c q[n][h*64+c]*Wp[h*64+c][e]
__device__ float g_Se[NH * NN * MM];      // Se[h][n][m] = q[n]·k'[m] (head slice) — already scaled + bp folded

// ============================================================
// K1: q/k'/v projections.  grid (48, 3), 256 threads.
// z: 0=q, 1=k' (bias bk+bp, scale 1/8), 2=v
// ============================================================
__global__ __launch_bounds__(256) void qkv_kernel(
    const float* __restrict__ in_q, const float* __restrict__ in_k, const float* __restrict__ in_v,
    const float* __restrict__ Wq, const float* __restrict__ bq,
    const float* __restrict__ Wk, const float* __restrict__ bk,
    const float* __restrict__ Wv, const float* __restrict__ bv,
    const float* __restrict__ bp)
{
    const int z  = blockIdx.y;
    const int n0 = blockIdx.x * 16;
    const int d  = threadIdx.x;

    const float* x = (z == 0) ? in_q : ((z == 1) ? in_k : in_v);
    const float* W = (z == 0) ? Wq   : ((z == 1) ? Wk   : Wv);
    float bias     = (z == 0) ? bq[d] : ((z == 1) ? (bk[d] + bp[d]) : bv[d]);
    const float scale = (z == 1) ? 0.125f : 1.0f;
    float* out = (z == 0) ? g_q : ((z == 1) ? g_k : g_v);

    // x tile transposed: xs[e][ni], ni stride 20 (float4-aligned, low conflict)
    __shared__ float xs[256 * 20];
    for (int idx = d; idx < 16 * 256; idx += 256) {
        int ni = idx >> 8, e = idx & 255;
        xs[e * 20 + ni] = x[(n0 + ni) * DM + e];
    }
    __syncthreads();

    float4 acc[4];
    #pragma unroll
    for (int g = 0; g < 4; g++) acc[g] = make_float4(0.f, 0.f, 0.f, 0.f);

    const float4* Wr = (const float4*)(W + d * DM);   // row d of W (x@W.T)
    #pragma unroll 4
    for (int e4 = 0; e4 < 64; e4++) {
        float4 wv = Wr[e4];
        float wa[4] = {wv.x, wv.y, wv.z, wv.w};
        #pragma unroll
        for (int k = 0; k < 4; k++) {
            int e = e4 * 4 + k;
            float w = wa[k];
            #pragma unroll
            for (int g = 0; g < 4; g++) {
                float4 xf = *(const float4*)&xs[e * 20 + g * 4];
                acc[g].x += xf.x * w;
                acc[g].y += xf.y * w;
                acc[g].z += xf.z * w;
                acc[g].w += xf.w * w;
            }
        }
    }
    #pragma unroll
    for (int g = 0; g < 4; g++) {
        out[(n0 + g * 4 + 0) * DM + d] = scale * (acc[g].x + bias);
        out[(n0 + g * 4 + 1) * DM + d] = scale * (acc[g].y + bias);
        out[(n0 + g * 4 + 2) * DM + d] = scale * (acc[g].z + bias);
        out[(n0 + g * 4 + 3) * DM + d] = scale * (acc[g].w + bias);
    }
}

// ============================================================
// K2: R[n][h][e] = 0.125 * q_h[n] @ Wp_h.   grid (48, 4), 256 threads.
// ============================================================
__global__ __launch_bounds__(256) void rproj_kernel(const float* __restrict__ Wp)
{
    const int n0 = blockIdx.x * 16;
    const int h  = blockIdx.y;
    const int e  = threadIdx.x;

    __shared__ float qs[64 * 20];   // qs[c][ni]
    for (int idx = e; idx < 16 * 64; idx += 256) {
        int ni = idx >> 6, c = idx & 63;
        qs[c * 20 + ni] = g_q[(n0 + ni) * DM + h * 64 + c];
    }
    __syncthreads();

    float4 acc[4];
    #pragma unroll
    for (int g = 0; g < 4; g++) acc[g] = make_float4(0.f, 0.f, 0.f, 0.f);

    #pragma unroll 4
    for (int c = 0; c < 64; c++) {
        float w = Wp[(h * 64 + c) * DM + e];   // coalesced across threads
        #pragma unroll
        for (int g = 0; g < 4; g++) {
            float4 xf = *(const float4*)&qs[c * 20 + g * 4];
            acc[g].x += xf.x * w;
            acc[g].y += xf.y * w;
            acc[g].z += xf.z * w;
            acc[g].w += xf.w * w;
        }
    }
    #pragma unroll
    for (int g = 0; g < 4; g++) {
        g_R[(n0 + g * 4 + 0) * (NH * DM) + h * DM + e] = 0.125f * acc[g].x;
        g_R[(n0 + g * 4 + 1) * (NH * DM) + h * DM + e] = 0.125f * acc[g].y;
        g_R[(n0 + g * 4 + 2) * (NH * DM) + h * DM + e] = 0.125f * acc[g].z;
        g_R[(n0 + g * 4 + 3) * (NH * DM) + h * DM + e] = 0.125f * acc[g].w;
    }
}

// ============================================================
// K3: Se[h][n][m] = q_h[n] · k'_h[m].   grid (12, 12, 4), 256 threads.
// 64x64 tile, K=64 single pass, 4x4 register tile per thread.
// ============================================================
__global__ __launch_bounds__(256) void se_kernel()
{
    const int m0 = blockIdx.x * 64;
    const int n0 = blockIdx.y * 64;
    const int h  = blockIdx.z;
    const int tid = threadIdx.x;

    __shared__ float qs[64 * 68];   // [c][n], stride 68 (float4-aligned)
    __shared__ float ks[64 * 68];   // [c][m]
    for (int idx = tid; idx < 64 * 64; idx += 256) {
        int i = idx >> 6, c = idx & 63;
        qs[c * 68 + i] = g_q[(n0 + i) * DM + h * 64 + c];
        ks[c * 68 + i] = g_k[(m0 + i) * DM + h * 64 + c];
    }
    __syncthreads();

    const int tx = tid & 15, ty = tid >> 4;
    float acc[4][4];
    #pragma unroll
    for (int i = 0; i < 4; i++)
        #pragma unroll
        for (int j = 0; j < 4; j++) acc[i][j] = 0.f;

    #pragma unroll 4
    for (int c = 0; c < 64; c++) {
        float4 a = *(const float4*)&qs[c * 68 + ty * 4];
        float4 b = *(const float4*)&ks[c * 68 + tx * 4];
        float av[4] = {a.x, a.y, a.z, a.w};
        float bv[4] = {b.x, b.y, b.z, b.w};
        #pragma unroll
        for (int i = 0; i < 4; i++)
            #pragma unroll
            for (int j = 0; j < 4; j++) acc[i][j] += av[i] * bv[j];
    }
    #pragma unroll
    for (int i = 0; i < 4; i++) {
        float4 r = make_float4(acc[i][0], acc[i][1], acc[i][2], acc[i][3]);
        *(float4*)&g_Se[((size_t)h * NN + (n0 + ty * 4 + i)) * MM + m0 + tx * 4] = r;
    }
}

// ============================================================
// K4: the big fused kernel.  grid 768 (one CTA per n), 256 threads (8 warps).
// score[h][m] = Se[h][n][m] + embed[n,m,:]·R[n,h,:]  (all pre-scaled)
// then softmax over m, write attn.
// ============================================================
__global__ __launch_bounds__(256) void attn_kernel(const float* __restrict__ emb,
                                                   float* __restrict__ attn_out)
{
    const int n    = blockIdx.x;
    const int tid  = threadIdx.x;
    const int lane = tid & 31;
    const int wrp  = tid >> 5;

    __shared__ float sc[NH * MM];     // 12 KB scores
    __shared__ float red[8];

    // init scores with Se (coalesced)
    #pragma unroll
    for (int h = 0; h < NH; h++)
        for (int m = tid; m < MM; m += 256)
            sc[h * MM + m] = g_Se[((size_t)h * NN + n) * MM + m];

    // R fragments in registers: lane owns e = lane*4..+3 and 128+lane*4..+3, all 4 heads
    const float4* Rr = (const float4*)(g_R + (size_t)n * NH * DM);
    float4 rA[4], rB[4];
    #pragma unroll
    for (int h = 0; h < NH; h++) {
        rA[h] = Rr[h * 64 + lane];
        rB[h] = Rr[h * 64 + 32 + lane];
    }
    __syncthreads();

    const float4* ebase = (const float4*)(emb + (size_t)n * MM * DM);
    for (int m = wrp; m < MM; m += 8) {
        const float4* er = ebase + (size_t)m * 64;
        float4 a0 = __ldcs(er + lane);        // streaming: don't pollute L2
        float4 a1 = __ldcs(er + 32 + lane);

        float acc[NH];
        #pragma unroll
        for (int h = 0; h < NH; h++) {
            acc[h] = a0.x * rA[h].x + a0.y * rA[h].y + a0.z * rA[h].z + a0.w * rA[h].w
                   + a1.x * rB[h].x + a1.y * rB[h].y + a1.z * rB[h].z + a1.w * rB[h].w;
        }

        // packed 4-value warp reduce (~18 instr instead of 40):
        // after two pack steps, lane&3 == h holds head-h partial; 3 butterflies finish.
        const unsigned FULL = 0xffffffffu;
        bool o1 = (lane & 1);
        float s = o1 ? acc[0] : acc[1];
        float r = __shfl_xor_sync(FULL, s, 1);
        float v01 = (o1 ? acc[1] : acc[0]) + r;
        s = o1 ? acc[2] : acc[3];
        r = __shfl_xor_sync(FULL, s, 1);
        float v23 = (o1 ? acc[3] : acc[2]) + r;
        bool o2 = (lane & 2);
        s = o2 ? v01 : v23;
        r = __shfl_xor_sync(FULL, s, 2);
        float u = (o2 ? v23 : v01) + r;
        u += __shfl_xor_sync(FULL, u, 4);
        u += __shfl_xor_sync(FULL, u, 8);
        u += __shfl_xor_sync(FULL, u, 16);

        if (lane < 4) sc[lane * MM + m] += u;
    }
    __syncthreads();

    // ---- softmax: 64 threads (2 warps) per head ----
    const int h = tid >> 6;
    const int t = tid & 63;

    float mx = -1e30f;
    for (int m = t; m < MM; m += 64) mx = fmaxf(mx, sc[h * MM + m]);
    #pragma unroll
    for (int d = 16; d; d >>= 1) mx = fmaxf(mx, __shfl_xor_sync(0xffffffffu, mx, d));
    if (lane == 0) red[wrp] = mx;
    __syncthreads();
    const float hmax = fmaxf(red[h * 2], red[h * 2 + 1]);

    float sum = 0.f;
    for (int m = t; m < MM; m += 64) {
        float e = __expf(sc[h * MM + m] - hmax);
        sc[h * MM + m] = e;
        sum += e;
    }
    #pragma unroll
    for (int d = 16; d; d >>= 1) sum += __shfl_xor_sync(0xffffffffu, sum, d);
    __syncthreads();                 // everyone done reading red (max)
    if (lane == 0) red[wrp] = sum;
    __syncthreads();
    const float inv = 1.0f / (red[h * 2] + red[h * 2 + 1]);

    float* ao = attn_out + ((size_t)h * NN + n) * MM;
    for (int m = t; m < MM; m += 64) ao[m] = sc[h * MM + m] * inv;
}

// ============================================================
// K5: hidden = attn @ v.  grid 192 (4 n-rows per CTA), 256 threads.
// thread = (h, c).  v staged in smem in 32-row tiles; attn via broadcast float4 LDS.
// ============================================================
__global__ __launch_bounds__(256) void av_kernel(const float* __restrict__ attn_g,
                                                 float* __restrict__ out_h)
{
    const int n0  = blockIdx.x * 4;
    const int tid = threadIdx.x;
    const int h   = tid >> 6;

    __shared__ float vs[32 * DM];     // 32 KB
    __shared__ float as_[4 * 4 * 32]; // [h][ni][m] 2 KB

    float acc[4] = {0.f, 0.f, 0.f, 0.f};

    for (int m0 = 0; m0 < MM; m0 += 32) {
        __syncthreads();
        const float4* vsrc = (const float4*)(g_v + m0 * DM);
        float4* vdst = (float4*)vs;
        #pragma unroll
        for (int i = tid; i < 32 * DM / 4; i += 256) vdst[i] = vsrc[i];
        #pragma unroll
        for (int i = tid; i < 512; i += 256) {
            int hh = i >> 7, rr = i & 127, ni = rr >> 5, mm = rr & 31;
            as_[i] = attn_g[((size_t)hh * NN + n0 + ni) * MM + m0 + mm];
        }
        __syncthreads();

        #pragma unroll
        for (int m4 = 0; m4 < 8; m4++) {
            float4 af0 = ((const float4*)as_)[(h * 4 + 0) * 8 + m4];
            float4 af1 = ((const float4*)as_)[(h * 4 + 1) * 8 + m4];
            float4 af2 = ((const float4*)as_)[(h * 4 + 2) * 8 + m4];
            float4 af3 = ((const float4*)as_)[(h * 4 + 3) * 8 + m4];
            float vv;
            vv = vs[(m4 * 4 + 0) * DM + tid];
            acc[0] += af0.x * vv; acc[1] += af1.x * vv; acc[2] += af2.x * vv; acc[3] += af3.x * vv;
            vv = vs[(m4 * 4 + 1) * DM + tid];
            acc[0] += af0.y * vv; acc[1] += af1.y * vv; acc[2] += af2.y * vv; acc[3] += af3.y * vv;
            vv = vs[(m4 * 4 + 2) * DM + tid];
            acc[0] += af0.z * vv; acc[1] += af1.z * vv; acc[2] += af2.z * vv; acc[3] += af3.z * vv;
            vv = vs[(m4 * 4 + 3) * DM + tid];
            acc[0] += af0.w * vv; acc[1] += af1.w * vv; acc[2] += af2.w * vv; acc[3] += af3.w * vv;
        }
    }
    #pragma unroll
    for (int ni = 0; ni < 4; ni++)
        out_h[(n0 + ni) * DM + tid] = acc[ni];
}

// ============================================================
// launch
// ============================================================
extern "C" void kernel_launch(void* const* d_in, const int* in_sizes, int n_in,
                              void* d_out, int out_size)
{
    const float* in_q = (const float*)d_in[0];
    const float* in_k = (const float*)d_in[1];
    const float* in_v = (const float*)d_in[2];
    const float* emb  = (const float*)d_in[3];
    const float* Wq   = (const float*)d_in[4];
    const float* bq   = (const float*)d_in[5];
    const float* Wk   = (const float*)d_in[6];
    const float* bk   = (const float*)d_in[7];
    const float* Wv   = (const float*)d_in[8];
    const float* bv   = (const float*)d_in[9];
    const float* Wp   = (const float*)d_in[10];
    const float* bp   = (const float*)d_in[11];

    float* out   = (float*)d_out;
    float* out_attn = out + NN * DM;   // hidden (196608) then attn (2359296)

    qkv_kernel<<<dim3(NN / 16, 3), 256>>>(in_q, in_k, in_v, Wq, bq, Wk, bk, Wv, bv, bp);
    rproj_kernel<<<dim3(NN / 16, NH), 256>>>(Wp);
    se_kernel<<<dim3(MM / 64, NN / 64, NH), 256>>>();
    attn_kernel<<<NN, 256>>>(emb, out_attn);
    av_kernel<<<NN / 4, 256>>>(out_attn, out);
}

// round 5
// speedup vs baseline: 1.1234x; 1.1234x over previous
#include <cuda_runtime.h>
#include <math.h>
#include <stdint.h>

#define DM 256
#define NH 4
#define HD 64
#define NN 768
#define MM 768

#define TILE_M 16
#define NBUF 2
#define NT (MM / TILE_M)            // 48 blocks
#define TILE_BYTES (TILE_M * DM * 4)  // 16384

// ---- scratch (static device globals: allocation-free) ----
__device__ float g_q[NN * DM];            // q = xq@Wq.T + bq
__device__ float g_k[NN * DM];            // k' = 0.125*(xk@Wk.T + bk + bp)
__device__ float g_v[NN * DM];            // v = xv@Wv.T + bv
__device__ float g_R[NN * NH * DM];       // R[n][h][e] = 0.125 * q_h[n] @ Wp_h
__device__ float g_Se[NH * NN * MM];      // Se[h][n][m] = q·k' (scaled, bp folded)

// ---- mbarrier / bulk-copy PTX helpers ----
__device__ __forceinline__ uint32_t smem_u32(const void* p) {
    return (uint32_t)__cvta_generic_to_shared(p);
}
#define MB_INIT(addr, cnt) \
    asm volatile("mbarrier.init.shared.b64 [%0], %1;" :: "r"(addr), "r"(cnt) : "memory")
#define MB_EXPECT_TX(addr, bytes) \
    asm volatile("mbarrier.arrive.expect_tx.shared.b64 _, [%0], %1;" :: "r"(addr), "r"(bytes) : "memory")
#define MB_ARRIVE(addr) \
    asm volatile("mbarrier.arrive.shared.b64 _, [%0];" :: "r"(addr) : "memory")
#define BULK_G2S(dst, src, bytes, mbar_) \
    asm volatile("cp.async.bulk.shared::cluster.global.mbarrier::complete_tx::bytes [%0], [%1], %2, [%3];" \
                 :: "r"(dst), "l"(src), "r"(bytes), "r"(mbar_) : "memory")

__device__ __forceinline__ void mbar_wait(uint32_t addr, uint32_t parity) {
    asm volatile(
        "{\n\t"
        ".reg .pred P;\n\t"
        "WL%=:\n\t"
        "mbarrier.try_wait.parity.acquire.cta.shared::cta.b64 P, [%0], %1, 0x989680;\n\t"
        "@P bra WD%=;\n\t"
        "bra WL%=;\n\t"
        "WD%=:\n\t"
        "}"
        :: "r"(addr), "r"(parity) : "memory");
}

// ============================================================
// K1: q/k'/v projections.  grid (48, 3), 256 threads.
// ============================================================
__global__ __launch_bounds__(256) void qkv_kernel(
    const float* __restrict__ in_q, const float* __restrict__ in_k, const float* __restrict__ in_v,
    const float* __restrict__ Wq, const float* __restrict__ bq,
    const float* __restrict__ Wk, const float* __restrict__ bk,
    const float* __restrict__ Wv, const float* __restrict__ bv,
    const float* __restrict__ bp)
{
    const int z  = blockIdx.y;
    const int n0 = blockIdx.x * 16;
    const int d  = threadIdx.x;

    const float* x = (z == 0) ? in_q : ((z == 1) ? in_k : in_v);
    const float* W = (z == 0) ? Wq   : ((z == 1) ? Wk   : Wv);
    float bias     = (z == 0) ? bq[d] : ((z == 1) ? (bk[d] + bp[d]) : bv[d]);
    const float scale = (z == 1) ? 0.125f : 1.0f;
    float* out = (z == 0) ? g_q : ((z == 1) ? g_k : g_v);

    __shared__ float xs[256 * 20];
    for (int idx = d; idx < 16 * 256; idx += 256) {
        int ni = idx >> 8, e = idx & 255;
        xs[e * 20 + ni] = x[(n0 + ni) * DM + e];
    }
    __syncthreads();

    float4 acc[4];
    #pragma unroll
    for (int g = 0; g < 4; g++) acc[g] = make_float4(0.f, 0.f, 0.f, 0.f);

    const float4* Wr = (const float4*)(W + d * DM);
    #pragma unroll 4
    for (int e4 = 0; e4 < 64; e4++) {
        float4 wv = Wr[e4];
        float wa[4] = {wv.x, wv.y, wv.z, wv.w};
        #pragma unroll
        for (int k = 0; k < 4; k++) {
            int e = e4 * 4 + k;
            float w = wa[k];
            #pragma unroll
            for (int g = 0; g < 4; g++) {
                float4 xf = *(const float4*)&xs[e * 20 + g * 4];
                acc[g].x += xf.x * w;
                acc[g].y += xf.y * w;
                acc[g].z += xf.z * w;
                acc[g].w += xf.w * w;
            }
        }
    }
    #pragma unroll
    for (int g = 0; g < 4; g++) {
        out[(n0 + g * 4 + 0) * DM + d] = scale * (acc[g].x + bias);
        out[(n0 + g * 4 + 1) * DM + d] = scale * (acc[g].y + bias);
        out[(n0 + g * 4 + 2) * DM + d] = scale * (acc[g].z + bias);
        out[(n0 + g * 4 + 3) * DM + d] = scale * (acc[g].w + bias);
    }
}

// ============================================================
// K2: R projection.  grid (48, 4), 256 threads.
// ============================================================
__global__ __launch_bounds__(256) void rproj_kernel(const float* __restrict__ Wp)
{
    const int n0 = blockIdx.x * 16;
    const int h  = blockIdx.y;
    const int e  = threadIdx.x;

    __shared__ float qs[64 * 20];
    for (int idx = e; idx < 16 * 64; idx += 256) {
        int ni = idx >> 6, c = idx & 63;
        qs[c * 20 + ni] = g_q[(n0 + ni) * DM + h * 64 + c];
    }
    __syncthreads();

    float4 acc[4];
    #pragma unroll
    for (int g = 0; g < 4; g++) acc[g] = make_float4(0.f, 0.f, 0.f, 0.f);

    #pragma unroll 4
    for (int c = 0; c < 64; c++) {
        float w = Wp[(h * 64 + c) * DM + e];
        #pragma unroll
        for (int g = 0; g < 4; g++) {
            float4 xf = *(const float4*)&qs[c * 20 + g * 4];
            acc[g].x += xf.x * w;
            acc[g].y += xf.y * w;
            acc[g].z += xf.z * w;
            acc[g].w += xf.w * w;
        }
    }
    #pragma unroll
    for (int g = 0; g < 4; g++) {
        g_R[(n0 + g * 4 + 0) * (NH * DM) + h * DM + e] = 0.125f * acc[g].x;
        g_R[(n0 + g * 4 + 1) * (NH * DM) + h * DM + e] = 0.125f * acc[g].y;
        g_R[(n0 + g * 4 + 2) * (NH * DM) + h * DM + e] = 0.125f * acc[g].z;
        g_R[(n0 + g * 4 + 3) * (NH * DM) + h * DM + e] = 0.125f * acc[g].w;
    }
}

// ============================================================
// K3: Se[h][n][m] = q_h[n] · k'_h[m].   grid (12, 12, 4), 256 threads.
// ============================================================
__global__ __launch_bounds__(256) void se_kernel()
{
    const int m0 = blockIdx.x * 64;
    const int n0 = blockIdx.y * 64;
    const int h  = blockIdx.z;
    const int tid = threadIdx.x;

    __shared__ float qs[64 * 68];
    __shared__ float ks[64 * 68];
    for (int idx = tid; idx < 64 * 64; idx += 256) {
        int i = idx >> 6, c = idx & 63;
        qs[c * 68 + i] = g_q[(n0 + i) * DM + h * 64 + c];
        ks[c * 68 + i] = g_k[(m0 + i) * DM + h * 64 + c];
    }
    __syncthreads();

    const int tx = tid & 15, ty = tid >> 4;
    float acc[4][4];
    #pragma unroll
    for (int i = 0; i < 4; i++)
        #pragma unroll
        for (int j = 0; j < 4; j++) acc[i][j] = 0.f;

    #pragma unroll 4
    for (int c = 0; c < 64; c++) {
        float4 a = *(const float4*)&qs[c * 68 + ty * 4];
        float4 b = *(const float4*)&ks[c * 68 + tx * 4];
        float av[4] = {a.x, a.y, a.z, a.w};
        float bv[4] = {b.x, b.y, b.z, b.w};
        #pragma unroll
        for (int i = 0; i < 4; i++)
            #pragma unroll
            for (int j = 0; j < 4; j++) acc[i][j] += av[i] * bv[j];
    }
    #pragma unroll
    for (int i = 0; i < 4; i++) {
        float4 r = make_float4(acc[i][0], acc[i][1], acc[i][2], acc[i][3]);
        *(float4*)&g_Se[((size_t)h * NN + (n0 + ty * 4 + i)) * MM + m0 + tx * 4] = r;
    }
}

// ============================================================
// K4: fused RPE-score + softmax, bulk-copy pipelined.
// grid 768 (one CTA per n), 256 threads (8 warps), 3 CTAs/SM.
// emb rows stream HBM -> SMEM via cp.async.bulk double buffer (16KB stages);
// consumers compute 4-head dots from SMEM (no long-scoreboard stalls).
// ============================================================
__global__ __launch_bounds__(256, 3) void attn_kernel(const float* __restrict__ emb,
                                                      float* __restrict__ attn_out)
{
    const int n    = blockIdx.x;
    const int tid  = threadIdx.x;
    const int lane = tid & 31;
    const int wrp  = tid >> 5;

    __shared__ float sc[NH * MM];                                // 12 KB
    __shared__ __align__(16) float buf[NBUF][TILE_M * DM];       // 32 KB
    __shared__ __align__(8) unsigned long long mbar[2 * NBUF];   // full0,full1,empty0,empty1
    __shared__ float red[8];

    const uint32_t fa0 = smem_u32(&mbar[0]);
    const uint32_t fa1 = smem_u32(&mbar[1]);
    const uint32_t ea0 = smem_u32(&mbar[2]);
    const uint32_t ea1 = smem_u32(&mbar[3]);
    const uint32_t ba0 = smem_u32(&buf[0][0]);
    const uint32_t ba1 = smem_u32(&buf[1][0]);

    if (tid == 0) {
        MB_INIT(fa0, 1); MB_INIT(fa1, 1);
        MB_INIT(ea0, 8); MB_INIT(ea1, 8);
    }

    // init scores with Se (coalesced) while barriers settle
    #pragma unroll
    for (int h = 0; h < NH; h++)
        for (int m = tid; m < MM; m += 256)
            sc[h * MM + m] = g_Se[((size_t)h * NN + n) * MM + m];

    // R fragments in registers: lane owns e = lane*4..+3 and 128+lane*4..+3
    const float4* Rr = (const float4*)(g_R + (size_t)n * NH * DM);
    float4 rA[NH], rB[NH];
    #pragma unroll
    for (int h = 0; h < NH; h++) {
        rA[h] = Rr[h * 64 + lane];
        rB[h] = Rr[h * 64 + 32 + lane];
    }
    __syncthreads();   // barriers initialized + sc ready

    const char* src = (const char*)(emb + (size_t)n * MM * DM);
    if (tid == 0) {
        MB_EXPECT_TX(fa0, TILE_BYTES);
        BULK_G2S(ba0, src, (uint32_t)TILE_BYTES, fa0);
        MB_EXPECT_TX(fa1, TILE_BYTES);
        BULK_G2S(ba1, src + TILE_BYTES, (uint32_t)TILE_BYTES, fa1);
    }

    const unsigned F = 0xffffffffu;
    const bool o1 = lane & 1, o2 = lane & 2, o4 = lane & 4;

    for (int t = 0; t < NT; t++) {
        const int s = t & 1;
        const uint32_t par = (uint32_t)((t >> 1) & 1);
        const uint32_t fa = s ? fa1 : fa0;
        const uint32_t ea = s ? ea1 : ea0;

        mbar_wait(fa, par);

        // each warp: 2 consecutive rows of this 16-row tile
        const float* bufp = buf[s];
        const float4* r0p = (const float4*)(bufp + (wrp * 2) * DM);
        const float4* r1p = (const float4*)(bufp + (wrp * 2 + 1) * DM);
        float4 a0 = r0p[lane], a1 = r0p[32 + lane];
        float4 b0 = r1p[lane], b1 = r1p[32 + lane];

        float acc0[NH], acc1[NH];
        #pragma unroll
        for (int h = 0; h < NH; h++) {
            acc0[h] = a0.x * rA[h].x + a0.y * rA[h].y + a0.z * rA[h].z + a0.w * rA[h].w
                    + a1.x * rB[h].x + a1.y * rB[h].y + a1.z * rB[h].z + a1.w * rB[h].w;
            acc1[h] = b0.x * rA[h].x + b0.y * rA[h].y + b0.z * rA[h].z + b0.w * rA[h].w
                    + b1.x * rB[h].x + b1.y * rB[h].y + b1.z * rB[h].z + b1.w * rB[h].w;
        }

        // packed reduce: 8 sums (2 rows x 4 heads) in 9 shuffles
        float sx, rx;
        sx = o1 ? acc0[0] : acc0[1]; rx = __shfl_xor_sync(F, sx, 1);
        float v01a = (o1 ? acc0[1] : acc0[0]) + rx;
        sx = o1 ? acc0[2] : acc0[3]; rx = __shfl_xor_sync(F, sx, 1);
        float v23a = (o1 ? acc0[3] : acc0[2]) + rx;
        sx = o1 ? acc1[0] : acc1[1]; rx = __shfl_xor_sync(F, sx, 1);
        float v01b = (o1 ? acc1[1] : acc1[0]) + rx;
        sx = o1 ? acc1[2] : acc1[3]; rx = __shfl_xor_sync(F, sx, 1);
        float v23b = (o1 ? acc1[3] : acc1[2]) + rx;

        sx = o2 ? v01a : v23a; rx = __shfl_xor_sync(F, sx, 2);
        float ua = (o2 ? v23a : v01a) + rx;
        sx = o2 ? v01b : v23b; rx = __shfl_xor_sync(F, sx, 2);
        float ub = (o2 ? v23b : v01b) + rx;

        sx = o4 ? ua : ub; rx = __shfl_xor_sync(F, sx, 4);
        float w = (o4 ? ub : ua) + rx;
        w += __shfl_xor_sync(F, w, 8);
        w += __shfl_xor_sync(F, w, 16);

        // lane<8: head = lane&3, row = (lane>>2)&1
        if (lane < 8)
            sc[(lane & 3) * MM + t * TILE_M + wrp * 2 + ((lane >> 2) & 1)] += w;

        __syncwarp();
        if (lane == 0) MB_ARRIVE(ea);

        // producer: refill this buffer for block t+2 once all warps released it
        if (tid == 0 && t + NBUF < NT) {
            mbar_wait(ea, par);
            MB_EXPECT_TX(fa, TILE_BYTES);
            BULK_G2S(s ? ba1 : ba0, src + (size_t)(t + NBUF) * TILE_BYTES,
                     (uint32_t)TILE_BYTES, fa);
        }
    }
    __syncthreads();

    // ---- softmax: 64 threads (2 warps) per head ----
    const int h = tid >> 6;
    const int t = tid & 63;

    float mx = -1e30f;
    for (int m = t; m < MM; m += 64) mx = fmaxf(mx, sc[h * MM + m]);
    #pragma unroll
    for (int d = 16; d; d >>= 1) mx = fmaxf(mx, __shfl_xor_sync(0xffffffffu, mx, d));
    if (lane == 0) red[wrp] = mx;
    __syncthreads();
    const float hmax = fmaxf(red[h * 2], red[h * 2 + 1]);

    float sum = 0.f;
    for (int m = t; m < MM; m += 64) {
        float e = __expf(sc[h * MM + m] - hmax);
        sc[h * MM + m] = e;
        sum += e;
    }
    #pragma unroll
    for (int d = 16; d; d >>= 1) sum += __shfl_xor_sync(0xffffffffu, sum, d);
    __syncthreads();
    if (lane == 0) red[wrp] = sum;
    __syncthreads();
    const float inv = 1.0f / (red[h * 2] + red[h * 2 + 1]);

    float* ao = attn_out + ((size_t)h * NN + n) * MM;
    for (int m = t; m < MM; m += 64) ao[m] = sc[h * MM + m] * inv;
}

// ============================================================
// K5: hidden = attn @ v.  grid 192, 256 threads.
// ============================================================
__global__ __launch_bounds__(256) void av_kernel(const float* __restrict__ attn_g,
                                                 float* __restrict__ out_h)
{
    const int n0  = blockIdx.x * 4;
    const int tid = threadIdx.x;
    const int h   = tid >> 6;

    __shared__ float vs[32 * DM];
    __shared__ float as_[4 * 4 * 32];

    float acc[4] = {0.f, 0.f, 0.f, 0.f};

    for (int m0 = 0; m0 < MM; m0 += 32) {
        __syncthreads();
        const float4* vsrc = (const float4*)(g_v + m0 * DM);
        float4* vdst = (float4*)vs;
        #pragma unroll
        for (int i = tid; i < 32 * DM / 4; i += 256) vdst[i] = vsrc[i];
        #pragma unroll
        for (int i = tid; i < 512; i += 256) {
            int hh = i >> 7, rr = i & 127, ni = rr >> 5, mm = rr & 31;
            as_[i] = attn_g[((size_t)hh * NN + n0 + ni) * MM + m0 + mm];
        }
        __syncthreads();

        #pragma unroll
        for (int m4 = 0; m4 < 8; m4++) {
            float4 af0 = ((const float4*)as_)[(h * 4 + 0) * 8 + m4];
            float4 af1 = ((const float4*)as_)[(h * 4 + 1) * 8 + m4];
            float4 af2 = ((const float4*)as_)[(h * 4 + 2) * 8 + m4];
            float4 af3 = ((const float4*)as_)[(h * 4 + 3) * 8 + m4];
            float vv;
            vv = vs[(m4 * 4 + 0) * DM + tid];
            acc[0] += af0.x * vv; acc[1] += af1.x * vv; acc[2] += af2.x * vv; acc[3] += af3.x * vv;
            vv = vs[(m4 * 4 + 1) * DM + tid];
            acc[0] += af0.y * vv; acc[1] += af1.y * vv; acc[2] += af2.y * vv; acc[3] += af3.y * vv;
            vv = vs[(m4 * 4 + 2) * DM + tid];
            acc[0] += af0.z * vv; acc[1] += af1.z * vv; acc[2] += af2.z * vv; acc[3] += af3.z * vv;
            vv = vs[(m4 * 4 + 3) * DM + tid];
            acc[0] += af0.w * vv; acc[1] += af1.w * vv; acc[2] += af2.w * vv; acc[3] += af3.w * vv;
        }
    }
    #pragma unroll
    for (int ni = 0; ni < 4; ni++)
        out_h[(n0 + ni) * DM + tid] = acc[ni];
}

// ============================================================
// launch
// ============================================================
extern "C" void kernel_launch(void* const* d_in, const int* in_sizes, int n_in,
                              void* d_out, int out_size)
{
    const float* in_q = (const float*)d_in[0];
    const float* in_k = (const float*)d_in[1];
    const float* in_v = (const float*)d_in[2];
    const float* emb  = (const float*)d_in[3];
    const float* Wq   = (const float*)d_in[4];
    const float* bq   = (const float*)d_in[5];
    const float* Wk   = (const float*)d_in[6];
    const float* bk   = (const float*)d_in[7];
    const float* Wv   = (const float*)d_in[8];
    const float* bv   = (const float*)d_in[9];
    const float* Wp   = (const float*)d_in[10];
    const float* bp   = (const float*)d_in[11];

    float* out      = (float*)d_out;
    float* out_attn = out + NN * DM;   // hidden (196608) then attn (2359296)

    qkv_kernel<<<dim3(NN / 16, 3), 256>>>(in_q, in_k, in_v, Wq, bq, Wk, bk, Wv, bv, bp);
    rproj_kernel<<<dim3(NN / 16, NH), 256>>>(Wp);
    se_kernel<<<dim3(MM / 64, NN / 64, NH), 256>>>();
    attn_kernel<<<NN, 256>>>(emb, out_attn);
    av_kernel<<<NN / 4, 256>>>(out_attn, out);
}

// round 6
// speedup vs baseline: 1.5693x; 1.3969x over previous
#include <cuda_runtime.h>
#include <math.h>
#include <stdint.h>

#define DM 256
#define NH 4
#define HD 64
#define NN 768
#define MM 768

#define TILE_M 16
#define NBUF 3
#define NT (MM / TILE_M)              // 48 tiles
#define TILE_BYTES (TILE_M * DM * 4)  // 16384
#define TILE_FLOATS (TILE_M * DM)     // 4096
// dynamic smem: sc (NH*MM floats) + buf (NBUF*TILE_FLOATS)
#define DYN_SMEM_BYTES ((NH * MM + NBUF * TILE_FLOATS) * 4)   // 61440

// ---- scratch (static device globals: allocation-free) ----
__device__ float g_q[NN * DM];
__device__ float g_k[NN * DM];            // k' = 0.125*(xk@Wk.T + bk + bp)
__device__ float g_v[NN * DM];
__device__ float g_R[NN * NH * DM];       // R[n][h][e] = 0.125 * q_h[n] @ Wp_h
__device__ float g_Se[NH * NN * MM];      // q·k' (scaled, bp folded)

// ---- mbarrier / bulk-copy PTX helpers ----
__device__ __forceinline__ uint32_t smem_u32(const void* p) {
    return (uint32_t)__cvta_generic_to_shared(p);
}
#define MB_INIT(addr, cnt) \
    asm volatile("mbarrier.init.shared.b64 [%0], %1;" :: "r"(addr), "r"(cnt) : "memory")
#define MB_EXPECT_TX(addr, bytes) \
    asm volatile("mbarrier.arrive.expect_tx.shared.b64 _, [%0], %1;" :: "r"(addr), "r"(bytes) : "memory")
#define MB_ARRIVE(addr) \
    asm volatile("mbarrier.arrive.shared.b64 _, [%0];" :: "r"(addr) : "memory")
#define BULK_G2S(dst, src, bytes, mbar_) \
    asm volatile("cp.async.bulk.shared::cluster.global.mbarrier::complete_tx::bytes [%0], [%1], %2, [%3];" \
                 :: "r"(dst), "l"(src), "r"(bytes), "r"(mbar_) : "memory")

__device__ __forceinline__ void mbar_wait(uint32_t addr, uint32_t parity) {
    asm volatile(
        "{\n\t"
        ".reg .pred P;\n\t"
        "WL%=:\n\t"
        "mbarrier.try_wait.parity.acquire.cta.shared::cta.b64 P, [%0], %1, 0x989680;\n\t"
        "@P bra WD%=;\n\t"
        "bra WL%=;\n\t"
        "WD%=:\n\t"
        "}"
        :: "r"(addr), "r"(parity) : "memory");
}

// ============================================================
// K1: q/k'/v projections.  grid (48, 3), 256 threads.
// ============================================================
__global__ __launch_bounds__(256) void qkv_kernel(
    const float* __restrict__ in_q, const float* __restrict__ in_k, const float* __restrict__ in_v,
    const float* __restrict__ Wq, const float* __restrict__ bq,
    const float* __restrict__ Wk, const float* __restrict__ bk,
    const float* __restrict__ Wv, const float* __restrict__ bv,
    const float* __restrict__ bp)
{
    const int z  = blockIdx.y;
    const int n0 = blockIdx.x * 16;
    const int d  = threadIdx.x;

    const float* x = (z == 0) ? in_q : ((z == 1) ? in_k : in_v);
    const float* W = (z == 0) ? Wq   : ((z == 1) ? Wk   : Wv);
    float bias     = (z == 0) ? bq[d] : ((z == 1) ? (bk[d] + bp[d]) : bv[d]);
    const float scale = (z == 1) ? 0.125f : 1.0f;
    float* out = (z == 0) ? g_q : ((z == 1) ? g_k : g_v);

    __shared__ float xs[256 * 20];
    for (int idx = d; idx < 16 * 256; idx += 256) {
        int ni = idx >> 8, e = idx & 255;
        xs[e * 20 + ni] = x[(n0 + ni) * DM + e];
    }
    __syncthreads();

    float4 acc[4];
    #pragma unroll
    for (int g = 0; g < 4; g++) acc[g] = make_float4(0.f, 0.f, 0.f, 0.f);

    const float4* Wr = (const float4*)(W + d * DM);
    #pragma unroll 4
    for (int e4 = 0; e4 < 64; e4++) {
        float4 wv = Wr[e4];
        float wa[4] = {wv.x, wv.y, wv.z, wv.w};
        #pragma unroll
        for (int k = 0; k < 4; k++) {
            int e = e4 * 4 + k;
            float w = wa[k];
            #pragma unroll
            for (int g = 0; g < 4; g++) {
                float4 xf = *(const float4*)&xs[e * 20 + g * 4];
                acc[g].x += xf.x * w;
                acc[g].y += xf.y * w;
                acc[g].z += xf.z * w;
                acc[g].w += xf.w * w;
            }
        }
    }
    #pragma unroll
    for (int g = 0; g < 4; g++) {
        out[(n0 + g * 4 + 0) * DM + d] = scale * (acc[g].x + bias);
        out[(n0 + g * 4 + 1) * DM + d] = scale * (acc[g].y + bias);
        out[(n0 + g * 4 + 2) * DM + d] = scale * (acc[g].z + bias);
        out[(n0 + g * 4 + 3) * DM + d] = scale * (acc[g].w + bias);
    }
}

// ============================================================
// K2: R projection.  grid (48, 4), 256 threads.
// ============================================================
__global__ __launch_bounds__(256) void rproj_kernel(const float* __restrict__ Wp)
{
    const int n0 = blockIdx.x * 16;
    const int h  = blockIdx.y;
    const int e  = threadIdx.x;

    __shared__ float qs[64 * 20];
    for (int idx = e; idx < 16 * 64; idx += 256) {
        int ni = idx >> 6, c = idx & 63;
        qs[c * 20 + ni] = g_q[(n0 + ni) * DM + h * 64 + c];
    }
    __syncthreads();

    float4 acc[4];
    #pragma unroll
    for (int g = 0; g < 4; g++) acc[g] = make_float4(0.f, 0.f, 0.f, 0.f);

    #pragma unroll 4
    for (int c = 0; c < 64; c++) {
        float w = Wp[(h * 64 + c) * DM + e];
        #pragma unroll
        for (int g = 0; g < 4; g++) {
            float4 xf = *(const float4*)&qs[c * 20 + g * 4];
            acc[g].x += xf.x * w;
            acc[g].y += xf.y * w;
            acc[g].z += xf.z * w;
            acc[g].w += xf.w * w;
        }
    }
    #pragma unroll
    for (int g = 0; g < 4; g++) {
        g_R[(n0 + g * 4 + 0) * (NH * DM) + h * DM + e] = 0.125f * acc[g].x;
        g_R[(n0 + g * 4 + 1) * (NH * DM) + h * DM + e] = 0.125f * acc[g].y;
        g_R[(n0 + g * 4 + 2) * (NH * DM) + h * DM + e] = 0.125f * acc[g].z;
        g_R[(n0 + g * 4 + 3) * (NH * DM) + h * DM + e] = 0.125f * acc[g].w;
    }
}

// ============================================================
// K3: Se[h][n][m] = q_h[n] · k'_h[m].   grid (12, 12, 4), 256 threads.
// ============================================================
__global__ __launch_bounds__(256) void se_kernel()
{
    const int m0 = blockIdx.x * 64;
    const int n0 = blockIdx.y * 64;
    const int h  = blockIdx.z;
    const int tid = threadIdx.x;

    __shared__ float qs[64 * 68];
    __shared__ float ks[64 * 68];
    for (int idx = tid; idx < 64 * 64; idx += 256) {
        int i = idx >> 6, c = idx & 63;
        qs[c * 68 + i] = g_q[(n0 + i) * DM + h * 64 + c];
        ks[c * 68 + i] = g_k[(m0 + i) * DM + h * 64 + c];
    }
    __syncthreads();

    const int tx = tid & 15, ty = tid >> 4;
    float acc[4][4];
    #pragma unroll
    for (int i = 0; i < 4; i++)
        #pragma unroll
        for (int j = 0; j < 4; j++) acc[i][j] = 0.f;

    #pragma unroll 4
    for (int c = 0; c < 64; c++) {
        float4 a = *(const float4*)&qs[c * 68 + ty * 4];
        float4 b = *(const float4*)&ks[c * 68 + tx * 4];
        float av[4] = {a.x, a.y, a.z, a.w};
        float bv[4] = {b.x, b.y, b.z, b.w};
        #pragma unroll
        for (int i = 0; i < 4; i++)
            #pragma unroll
            for (int j = 0; j < 4; j++) acc[i][j] += av[i] * bv[j];
    }
    #pragma unroll
    for (int i = 0; i < 4; i++) {
        float4 r = make_float4(acc[i][0], acc[i][1], acc[i][2], acc[i][3]);
        *(float4*)&g_Se[((size_t)h * NN + (n0 + ty * 4 + i)) * MM + m0 + tx * 4] = r;
    }
}

// ============================================================
// K4: fused RPE-score + softmax, depth-3 bulk-copy pipeline.
// grid 768 (one CTA per n), 256 threads (8 warps), 3 CTAs/SM.
// dynamic smem: sc[NH*MM] then buf[NBUF][TILE_FLOATS].
// ============================================================
__global__ __launch_bounds__(256, 3) void attn_kernel(const float* __restrict__ emb,
                                                      float* __restrict__ attn_out)
{
    extern __shared__ __align__(16) float dyn[];
    float* sc  = dyn;                 // NH*MM = 3072 floats (12 KB)
    float* buf = dyn + NH * MM;       // NBUF * 4096 floats (48 KB)

    const int n    = blockIdx.x;
    const int tid  = threadIdx.x;
    const int lane = tid & 31;
    const int wrp  = tid >> 5;

    __shared__ __align__(8) unsigned long long mbar[2 * NBUF];  // full[3], empty[3]
    __shared__ float red[8];

    const uint32_t mb   = smem_u32(mbar);
    const uint32_t bufa = smem_u32(buf);

    if (tid == 0) {
        #pragma unroll
        for (int i = 0; i < NBUF; i++) {
            MB_INIT(mb + i * 8, 1);               // full[i]
            MB_INIT(mb + (NBUF + i) * 8, 8);      // empty[i]
        }
    }

    // init scores with Se (coalesced) while barriers settle
    #pragma unroll
    for (int h = 0; h < NH; h++)
        for (int m = tid; m < MM; m += 256)
            sc[h * MM + m] = g_Se[((size_t)h * NN + n) * MM + m];

    // R fragments in registers: lane owns e = lane*4..+3 and 128+lane*4..+3
    const float4* Rr = (const float4*)(g_R + (size_t)n * NH * DM);
    float4 rA[NH], rB[NH];
    #pragma unroll
    for (int h = 0; h < NH; h++) {
        rA[h] = Rr[h * 64 + lane];
        rB[h] = Rr[h * 64 + 32 + lane];
    }
    __syncthreads();   // barriers initialized + sc ready

    const char* src = (const char*)(emb + (size_t)n * MM * DM);
    if (tid == 0) {
        #pragma unroll
        for (int i = 0; i < NBUF; i++) {
            MB_EXPECT_TX(mb + i * 8, TILE_BYTES);
            BULK_G2S(bufa + i * TILE_BYTES, src + (size_t)i * TILE_BYTES,
                     (uint32_t)TILE_BYTES, mb + i * 8);
        }
    }

    const unsigned F = 0xffffffffu;
    const bool o1 = lane & 1, o2 = lane & 2, o4 = lane & 4;

    int s = 0;
    uint32_t par = 0;
    for (int t = 0; t < NT; t++) {
        const uint32_t fa = mb + s * 8;
        const uint32_t ea = mb + (NBUF + s) * 8;

        mbar_wait(fa, par);

        // each warp: 2 consecutive rows of this 16-row tile
        const float* bufp = buf + s * TILE_FLOATS;
        const float4* r0p = (const float4*)(bufp + (wrp * 2) * DM);
        const float4* r1p = (const float4*)(bufp + (wrp * 2 + 1) * DM);
        float4 a0 = r0p[lane], a1 = r0p[32 + lane];
        float4 b0 = r1p[lane], b1 = r1p[32 + lane];

        float acc0[NH], acc1[NH];
        #pragma unroll
        for (int h = 0; h < NH; h++) {
            acc0[h] = a0.x * rA[h].x + a0.y * rA[h].y + a0.z * rA[h].z + a0.w * rA[h].w
                    + a1.x * rB[h].x + a1.y * rB[h].y + a1.z * rB[h].z + a1.w * rB[h].w;
            acc1[h] = b0.x * rA[h].x + b0.y * rA[h].y + b0.z * rA[h].z + b0.w * rA[h].w
                    + b1.x * rB[h].x + b1.y * rB[h].y + b1.z * rB[h].z + b1.w * rB[h].w;
        }

        // packed reduce: 8 sums (2 rows x 4 heads) in 9 shuffles
        float sx, rx;
        sx = o1 ? acc0[0] : acc0[1]; rx = __shfl_xor_sync(F, sx, 1);
        float v01a = (o1 ? acc0[1] : acc0[0]) + rx;
        sx = o1 ? acc0[2] : acc0[3]; rx = __shfl_xor_sync(F, sx, 1);
        float v23a = (o1 ? acc0[3] : acc0[2]) + rx;
        sx = o1 ? acc1[0] : acc1[1]; rx = __shfl_xor_sync(F, sx, 1);
        float v01b = (o1 ? acc1[1] : acc1[0]) + rx;
        sx = o1 ? acc1[2] : acc1[3]; rx = __shfl_xor_sync(F, sx, 1);
        float v23b = (o1 ? acc1[3] : acc1[2]) + rx;

        sx = o2 ? v01a : v23a; rx = __shfl_xor_sync(F, sx, 2);
        float ua = (o2 ? v23a : v01a) + rx;
        sx = o2 ? v01b : v23b; rx = __shfl_xor_sync(F, sx, 2);
        float ub = (o2 ? v23b : v01b) + rx;

        sx = o4 ? ua : ub; rx = __shfl_xor_sync(F, sx, 4);
        float w = (o4 ? ub : ua) + rx;
        w += __shfl_xor_sync(F, w, 8);
        w += __shfl_xor_sync(F, w, 16);

        // lane<8: head = lane&3, row = (lane>>2)&1
        if (lane < 8)
            sc[(lane & 3) * MM + t * TILE_M + wrp * 2 + ((lane >> 2) & 1)] += w;

        __syncwarp();
        if (lane == 0) MB_ARRIVE(ea);

        // producer: refill buffer s for tile t+NBUF once all warps released it.
        // empty[s]'s (t/NBUF)-th completion has parity == par (same counter).
        if (tid == 0 && t + NBUF < NT) {
            mbar_wait(ea, par);
            MB_EXPECT_TX(fa, TILE_BYTES);
            BULK_G2S(bufa + s * TILE_BYTES, src + (size_t)(t + NBUF) * TILE_BYTES,
                     (uint32_t)TILE_BYTES, fa);
        }

        if (++s == NBUF) { s = 0; par ^= 1; }
    }
    __syncthreads();

    // ---- softmax: 64 threads (2 warps) per head ----
    const int h = tid >> 6;
    const int t = tid & 63;

    float mx = -1e30f;
    for (int m = t; m < MM; m += 64) mx = fmaxf(mx, sc[h * MM + m]);
    #pragma unroll
    for (int d = 16; d; d >>= 1) mx = fmaxf(mx, __shfl_xor_sync(0xffffffffu, mx, d));
    if (lane == 0) red[wrp] = mx;
    __syncthreads();
    const float hmax = fmaxf(red[h * 2], red[h * 2 + 1]);

    float sum = 0.f;
    for (int m = t; m < MM; m += 64) {
        float e = __expf(sc[h * MM + m] - hmax);
        sc[h * MM + m] = e;
        sum += e;
    }
    #pragma unroll
    for (int d = 16; d; d >>= 1) sum += __shfl_xor_sync(0xffffffffu, sum, d);
    __syncthreads();
    if (lane == 0) red[wrp] = sum;
    __syncthreads();
    const float inv = 1.0f / (red[h * 2] + red[h * 2 + 1]);

    float* ao = attn_out + ((size_t)h * NN + n) * MM;
    for (int m = t; m < MM; m += 64) ao[m] = sc[h * MM + m] * inv;
}

// ============================================================
// K5: hidden = attn @ v.  grid 192, 256 threads.
// ============================================================
__global__ __launch_bounds__(256) void av_kernel(const float* __restrict__ attn_g,
                                                 float* __restrict__ out_h)
{
    const int n0  = blockIdx.x * 4;
    const int tid = threadIdx.x;
    const int h   = tid >> 6;

    __shared__ float vs[32 * DM];
    __shared__ float as_[4 * 4 * 32];

    float acc[4] = {0.f, 0.f, 0.f, 0.f};

    for (int m0 = 0; m0 < MM; m0 += 32) {
        __syncthreads();
        const float4* vsrc = (const float4*)(g_v + m0 * DM);
        float4* vdst = (float4*)vs;
        #pragma unroll
        for (int i = tid; i < 32 * DM / 4; i += 256) vdst[i] = vsrc[i];
        #pragma unroll
        for (int i = tid; i < 512; i += 256) {
            int hh = i >> 7, rr = i & 127, ni = rr >> 5, mm = rr & 31;
            as_[i] = attn_g[((size_t)hh * NN + n0 + ni) * MM + m0 + mm];
        }
        __syncthreads();

        #pragma unroll
        for (int m4 = 0; m4 < 8; m4++) {
            float4 af0 = ((const float4*)as_)[(h * 4 + 0) * 8 + m4];
            float4 af1 = ((const float4*)as_)[(h * 4 + 1) * 8 + m4];
            float4 af2 = ((const float4*)as_)[(h * 4 + 2) * 8 + m4];
            float4 af3 = ((const float4*)as_)[(h * 4 + 3) * 8 + m4];
            float vv;
            vv = vs[(m4 * 4 + 0) * DM + tid];
            acc[0] += af0.x * vv; acc[1] += af1.x * vv; acc[2] += af2.x * vv; acc[3] += af3.x * vv;
            vv = vs[(m4 * 4 + 1) * DM + tid];
            acc[0] += af0.y * vv; acc[1] += af1.y * vv; acc[2] += af2.y * vv; acc[3] += af3.y * vv;
            vv = vs[(m4 * 4 + 2) * DM + tid];
            acc[0] += af0.z * vv; acc[1] += af1.z * vv; acc[2] += af2.z * vv; acc[3] += af3.z * vv;
            vv = vs[(m4 * 4 + 3) * DM + tid];
            acc[0] += af0.w * vv; acc[1] += af1.w * vv; acc[2] += af2.w * vv; acc[3] += af3.w * vv;
        }
    }
    #pragma unroll
    for (int ni = 0; ni < 4; ni++)
        out_h[(n0 + ni) * DM + tid] = acc[ni];
}

// ============================================================
// launch
// ============================================================
extern "C" void kernel_launch(void* const* d_in, const int* in_sizes, int n_in,
                              void* d_out, int out_size)
{
    const float* in_q = (const float*)d_in[0];
    const float* in_k = (const float*)d_in[1];
    const float* in_v = (const float*)d_in[2];
    const float* emb  = (const float*)d_in[3];
    const float* Wq   = (const float*)d_in[4];
    const float* bq   = (const float*)d_in[5];
    const float* Wk   = (const float*)d_in[6];
    const float* bk   = (const float*)d_in[7];
    const float* Wv   = (const float*)d_in[8];
    const float* bv   = (const float*)d_in[9];
    const float* Wp   = (const float*)d_in[10];
    const float* bp   = (const float*)d_in[11];

    float* out      = (float*)d_out;
    float* out_attn = out + NN * DM;   // hidden (196608) then attn (2359296)

    static bool attr_set = false;
    if (!attr_set) {
        cudaFuncSetAttribute(attn_kernel, cudaFuncAttributeMaxDynamicSharedMemorySize,
                             DYN_SMEM_BYTES);
        attr_set = true;
    }

    qkv_kernel<<<dim3(NN / 16, 3), 256>>>(in_q, in_k, in_v, Wq, bq, Wk, bk, Wv, bv, bp);
    rproj_kernel<<<dim3(NN / 16, NH), 256>>>(Wp);
    se_kernel<<<dim3(MM / 64, NN / 64, NH), 256>>>();
    attn_kernel<<<NN, 256, DYN_SMEM_BYTES>>>(emb, out_attn);
    av_kernel<<<NN / 4, 256>>>(out_attn, out);
}